// round 1
// baseline (speedup 1.0000x reference)
#include <cuda_runtime.h>
#include <cuda_bf16.h>

#define NN 50000
#define EE 800000
#define DMM 128
#define LLN 6
#define FFD 512
#define EPSV 1e-5f

// ---------------- device-global scratch (no allocs allowed) ----------------
__device__ float g_x[NN * DMM];            // node features (current)
__device__ float g_qkv[NN * 3 * DMM];      // packed [q|k|v] per node
__device__ float g_h1[NN * FFD];           // FFN hidden
__device__ float g_h2[NN * DMM];           // FFN out
__device__ float g_Wqkv[LLN * DMM * 3 * DMM]; // packed per-layer [K][3*DM] weights
__device__ int   g_deg[NN];
__device__ int   g_off[NN + 1];
__device__ int   g_cur[NN];
__device__ int   g_eid[EE];

// ---------------- CSR build ----------------
__global__ void zero_deg_kernel() {
    int i = blockIdx.x * 256 + threadIdx.x;
    if (i < NN) g_deg[i] = 0;
}

__global__ void count_kernel(const int* __restrict__ ei) {
    int e = blockIdx.x * 256 + threadIdx.x;
    if (e < EE) atomicAdd(&g_deg[ei[EE + e]], 1);
}

// single-block exclusive scan over g_deg -> g_off, g_cur
__global__ void scan_kernel() {
    __shared__ int sh[1024];
    int tid = threadIdx.x;
    int running = 0;
    for (int base = 0; base < NN; base += 1024) {
        int i = base + tid;
        int v = (i < NN) ? g_deg[i] : 0;
        sh[tid] = v;
        __syncthreads();
        for (int s = 1; s < 1024; s <<= 1) {
            int t = (tid >= s) ? sh[tid - s] : 0;
            __syncthreads();
            sh[tid] += t;
            __syncthreads();
        }
        int incl = sh[tid];
        if (i < NN) {
            int ex = running + incl - v;
            g_off[i] = ex;
            g_cur[i] = ex;
        }
        int tot = sh[1023];
        __syncthreads();
        running += tot;
    }
    if (tid == 0) g_off[NN] = running;
}

__global__ void fill_kernel(const int* __restrict__ ei) {
    int e = blockIdx.x * 256 + threadIdx.x;
    if (e < EE) {
        int d = ei[EE + e];
        int p = atomicAdd(&g_cur[d], 1);
        g_eid[p] = e;
    }
}

// ---------------- pack Wq|Wk|Wv into one [K][384] matrix per layer ----------------
__global__ void pack_kernel(const float* __restrict__ Wq, const float* __restrict__ Wk,
                            const float* __restrict__ Wv) {
    int idx = blockIdx.x * 256 + threadIdx.x;
    const int TOT = LLN * DMM * 3 * DMM;
    if (idx >= TOT) return;
    int l = idx / (DMM * 384);
    int rem = idx % (DMM * 384);
    int k = rem / 384;
    int c = rem % 384;
    float v;
    if (c < 128)      v = Wq[(l * DMM + k) * DMM + c];
    else if (c < 256) v = Wk[(l * DMM + k) * DMM + (c - 128)];
    else              v = Wv[(l * DMM + k) * DMM + (c - 256)];
    g_Wqkv[idx] = v;
}

// ---------------- embedding: x = nf @ emb_W + emb_b ----------------
__global__ void embed_kernel(const float* __restrict__ nf, const float* __restrict__ W,
                             const float* __restrict__ b) {
    __shared__ float s[20];
    int node = blockIdx.x;
    int c = threadIdx.x;
    if (c < 20) s[c] = nf[node * 20 + c];
    __syncthreads();
    float acc = b[c];
#pragma unroll
    for (int k = 0; k < 20; k++) acc += s[k] * W[k * DMM + c];
    g_x[node * DMM + c] = acc;
}

// ---------------- generic fp32 SGEMM: C = act(A[MxK] @ B[KxN] + bias) ----------------
// BM=128, BN=128, BK=8, TM=TN=8, 256 threads
template <bool RELU>
__global__ __launch_bounds__(256) void sgemm_kernel(const float* __restrict__ A,
                                                    const float* __restrict__ B,
                                                    const float* __restrict__ bias,
                                                    float* __restrict__ C,
                                                    int M, int Nc, int K) {
    const int BM = 128, BN = 128, BK = 8;
    __shared__ float As[BK][BM];
    __shared__ float Bs[BK][BN];
    int tid = threadIdx.x;
    int cRow = blockIdx.y, cCol = blockIdx.x;
    int tRow = tid / 16, tCol = tid % 16;

    int aRow = tid / 2;
    int aCol = (tid % 2) * 4;
    int bRow = tid / 32;
    int bCol = (tid % 32) * 4;

    const float* Ablk = A + (size_t)cRow * BM * K;
    const float* Bblk = B + (size_t)cCol * BN;

    float acc[8][8];
#pragma unroll
    for (int i = 0; i < 8; i++)
#pragma unroll
        for (int j = 0; j < 8; j++) acc[i][j] = 0.f;

    int gARow = cRow * BM + aRow;

    for (int k0 = 0; k0 < K; k0 += BK) {
        float4 av = (gARow < M) ? *(const float4*)(Ablk + (size_t)aRow * K + k0 + aCol)
                                : make_float4(0.f, 0.f, 0.f, 0.f);
        As[aCol + 0][aRow] = av.x;
        As[aCol + 1][aRow] = av.y;
        As[aCol + 2][aRow] = av.z;
        As[aCol + 3][aRow] = av.w;
        float4 bv = *(const float4*)(Bblk + (size_t)(k0 + bRow) * Nc + bCol);
        *(float4*)&Bs[bRow][bCol] = bv;
        __syncthreads();
#pragma unroll
        for (int k = 0; k < BK; k++) {
            float regM[8], regN[8];
            *(float4*)&regM[0] = *(float4*)&As[k][tRow * 8];
            *(float4*)&regM[4] = *(float4*)&As[k][tRow * 8 + 4];
            *(float4*)&regN[0] = *(float4*)&Bs[k][tCol * 8];
            *(float4*)&regN[4] = *(float4*)&Bs[k][tCol * 8 + 4];
#pragma unroll
            for (int i = 0; i < 8; i++)
#pragma unroll
                for (int j = 0; j < 8; j++) acc[i][j] += regM[i] * regN[j];
        }
        __syncthreads();
    }

#pragma unroll
    for (int i = 0; i < 8; i++) {
        int row = cRow * BM + tRow * 8 + i;
        if (row >= M) continue;
#pragma unroll
        for (int j = 0; j < 8; j += 4) {
            int col = cCol * BN + tCol * 8 + j;
            float4 c;
            c.x = acc[i][j + 0];
            c.y = acc[i][j + 1];
            c.z = acc[i][j + 2];
            c.w = acc[i][j + 3];
            if (bias != nullptr) {
                float4 bb = *(const float4*)&bias[col];
                c.x += bb.x; c.y += bb.y; c.z += bb.z; c.w += bb.w;
            }
            if (RELU) {
                c.x = fmaxf(c.x, 0.f); c.y = fmaxf(c.y, 0.f);
                c.z = fmaxf(c.z, 0.f); c.w = fmaxf(c.w, 0.f);
            }
            *(float4*)&C[(size_t)row * Nc + col] = c;
        }
    }
}

// ---------------- edge attention + aggregation + residual + LN (warp per node) -------
__global__ __launch_bounds__(256) void agg_kernel(const float* __restrict__ edge_attr,
                                                  const int* __restrict__ edge_index,
                                                  const float* __restrict__ eW1,
                                                  const float* __restrict__ eb1,
                                                  const float* __restrict__ eW2,
                                                  const float* __restrict__ eb2,
                                                  const float* __restrict__ lg,
                                                  const float* __restrict__ lb) {
    __shared__ float sW1[48];
    __shared__ float sb1[16];
    __shared__ float sW2[16 * 128];
    __shared__ float sb2[128];
    __shared__ float sg[128];
    __shared__ float sb[128];
    int tid = threadIdx.x;
    if (tid < 48) sW1[tid] = eW1[tid];
    if (tid < 16) sb1[tid] = eb1[tid];
    for (int i = tid; i < 2048; i += 256) sW2[i] = eW2[i];
    if (tid < 128) {
        sb2[tid] = eb2[tid];
        sg[tid] = lg[tid];
        sb[tid] = lb[tid];
    }
    __syncthreads();

    int warp = tid / 32, lane = tid % 32;
    int node = blockIdx.x * 8 + warp;
    if (node >= NN) return;

    const int* srcArr = edge_index;  // row 0 = src
    int d0 = lane * 4;
    float4 q = *(const float4*)&g_qkv[(size_t)node * 384 + d0];
    float4 acc = make_float4(0.f, 0.f, 0.f, 0.f);
    int beg = g_off[node], end = g_off[node + 1];

    for (int t = beg; t < end; t++) {
        int e = g_eid[t];
        int j = srcArr[e];
        float ea0 = edge_attr[e * 3 + 0];
        float ea1 = edge_attr[e * 3 + 1];
        float ea2 = edge_attr[e * 3 + 2];
        // hidden = relu(ea @ eW1 + eb1): 16 values, computed redundantly per lane
        float hr[16];
#pragma unroll
        for (int u = 0; u < 16; u++) {
            float h = ea0 * sW1[u] + ea1 * sW1[16 + u] + ea2 * sW1[32 + u] + sb1[u];
            hr[u] = fmaxf(h, 0.f);
        }
        // ee for this lane's 4 dims
        float4 ee = *(const float4*)&sb2[d0];
#pragma unroll
        for (int u = 0; u < 16; u++) {
            float4 w = *(const float4*)&sW2[u * 128 + d0];
            ee.x += hr[u] * w.x;
            ee.y += hr[u] * w.y;
            ee.z += hr[u] * w.z;
            ee.w += hr[u] * w.w;
        }
        float4 k4 = *(const float4*)&g_qkv[(size_t)j * 384 + 128 + d0];
        float p = q.x * (k4.x + ee.x) + q.y * (k4.y + ee.y) +
                  q.z * (k4.z + ee.z) + q.w * (k4.w + ee.w);
        // reduce dot within the 4-lane head group
        p += __shfl_xor_sync(0xffffffffu, p, 1);
        p += __shfl_xor_sync(0xffffffffu, p, 2);
        p *= 0.25f;  // 1/sqrt(16)
        // softmax over 8 heads: head values replicated x4; xor over {4,8,16}
        // hits exactly one lane per head
        float m = p;
        m = fmaxf(m, __shfl_xor_sync(0xffffffffu, m, 4));
        m = fmaxf(m, __shfl_xor_sync(0xffffffffu, m, 8));
        m = fmaxf(m, __shfl_xor_sync(0xffffffffu, m, 16));
        float ex = __expf(p - m);
        float sum = ex;
        sum += __shfl_xor_sync(0xffffffffu, sum, 4);
        sum += __shfl_xor_sync(0xffffffffu, sum, 8);
        sum += __shfl_xor_sync(0xffffffffu, sum, 16);
        float attn = ex / sum;
        float4 v4 = *(const float4*)&g_qkv[(size_t)j * 384 + 256 + d0];
        acc.x += attn * v4.x;
        acc.y += attn * v4.y;
        acc.z += attn * v4.z;
        acc.w += attn * v4.w;
    }

    // residual + LayerNorm
    float4 xr = *(const float4*)&g_x[(size_t)node * DMM + d0];
    float4 r;
    r.x = xr.x + acc.x; r.y = xr.y + acc.y;
    r.z = xr.z + acc.z; r.w = xr.w + acc.w;
    float s1 = r.x + r.y + r.z + r.w;
    float s2 = r.x * r.x + r.y * r.y + r.z * r.z + r.w * r.w;
#pragma unroll
    for (int s = 16; s >= 1; s >>= 1) {
        s1 += __shfl_xor_sync(0xffffffffu, s1, s);
        s2 += __shfl_xor_sync(0xffffffffu, s2, s);
    }
    float mu = s1 * (1.f / 128.f);
    float var = s2 * (1.f / 128.f) - mu * mu;
    float inv = rsqrtf(var + EPSV);
    float4 o;
    o.x = (r.x - mu) * inv * sg[d0 + 0] + sb[d0 + 0];
    o.y = (r.y - mu) * inv * sg[d0 + 1] + sb[d0 + 1];
    o.z = (r.z - mu) * inv * sg[d0 + 2] + sb[d0 + 2];
    o.w = (r.w - mu) * inv * sg[d0 + 3] + sb[d0 + 3];
    *(float4*)&g_x[(size_t)node * DMM + d0] = o;
}

// ---------------- FFN residual + LN (warp per node) ----------------
__global__ __launch_bounds__(256) void resln_kernel(const float* __restrict__ lg,
                                                    const float* __restrict__ lb,
                                                    float* __restrict__ out,
                                                    float* __restrict__ xkeep) {
    int tid = threadIdx.x;
    int warp = tid / 32, lane = tid % 32;
    int node = blockIdx.x * 8 + warp;
    if (node >= NN) return;
    int d0 = lane * 4;
    float4 a = *(const float4*)&g_x[(size_t)node * DMM + d0];
    float4 h = *(const float4*)&g_h2[(size_t)node * DMM + d0];
    float4 r;
    r.x = a.x + h.x; r.y = a.y + h.y; r.z = a.z + h.z; r.w = a.w + h.w;
    float s1 = r.x + r.y + r.z + r.w;
    float s2 = r.x * r.x + r.y * r.y + r.z * r.z + r.w * r.w;
#pragma unroll
    for (int s = 16; s >= 1; s >>= 1) {
        s1 += __shfl_xor_sync(0xffffffffu, s1, s);
        s2 += __shfl_xor_sync(0xffffffffu, s2, s);
    }
    float mu = s1 * (1.f / 128.f);
    float var = s2 * (1.f / 128.f) - mu * mu;
    float inv = rsqrtf(var + EPSV);
    float4 g4 = *(const float4*)&lg[d0];
    float4 b4 = *(const float4*)&lb[d0];
    float4 o;
    o.x = (r.x - mu) * inv * g4.x + b4.x;
    o.y = (r.y - mu) * inv * g4.y + b4.y;
    o.z = (r.z - mu) * inv * g4.z + b4.z;
    o.w = (r.w - mu) * inv * g4.w + b4.w;
    *(float4*)&out[(size_t)node * DMM + d0] = o;
    if (xkeep != out) *(float4*)&xkeep[(size_t)node * DMM + d0] = o;
}

// ---------------- launch ----------------
extern "C" void kernel_launch(void* const* d_in, const int* in_sizes, int n_in,
                              void* d_out, int out_size) {
    const float* nf        = (const float*)d_in[0];
    const float* edge_attr = (const float*)d_in[1];
    const int*   edge_idx  = (const int*)d_in[2];
    const float* emb_W     = (const float*)d_in[3];
    const float* emb_b     = (const float*)d_in[4];
    const float* Wq        = (const float*)d_in[5];
    const float* Wk        = (const float*)d_in[6];
    const float* Wv        = (const float*)d_in[7];
    const float* eW1       = (const float*)d_in[8];
    const float* eb1       = (const float*)d_in[9];
    const float* eW2       = (const float*)d_in[10];
    const float* eb2       = (const float*)d_in[11];
    const float* ln_g      = (const float*)d_in[12];
    const float* ln_b      = (const float*)d_in[13];
    const float* fW1       = (const float*)d_in[14];
    const float* fb1       = (const float*)d_in[15];
    const float* fW2       = (const float*)d_in[16];
    const float* fb2       = (const float*)d_in[17];

    float *x, *qkv, *h1, *h2, *wqkv;
    cudaGetSymbolAddress((void**)&x, g_x);
    cudaGetSymbolAddress((void**)&qkv, g_qkv);
    cudaGetSymbolAddress((void**)&h1, g_h1);
    cudaGetSymbolAddress((void**)&h2, g_h2);
    cudaGetSymbolAddress((void**)&wqkv, g_Wqkv);

    // CSR build (by dst)
    zero_deg_kernel<<<(NN + 255) / 256, 256>>>();
    count_kernel<<<(EE + 255) / 256, 256>>>(edge_idx);
    scan_kernel<<<1, 1024>>>();
    fill_kernel<<<(EE + 255) / 256, 256>>>(edge_idx);

    // pack weights
    {
        const int TOT = LLN * DMM * 3 * DMM;
        pack_kernel<<<(TOT + 255) / 256, 256>>>(Wq, Wk, Wv);
    }

    // embedding
    embed_kernel<<<NN, 128>>>(nf, emb_W, emb_b);

    const int gRows = (NN + 127) / 128;  // 391
    for (int l = 0; l < LLN; l++) {
        // QKV (fused 3 GEMMs): [N,128] @ [128,384]
        sgemm_kernel<false><<<dim3(3, gRows), 256>>>(
            x, wqkv + (size_t)l * DMM * 384, nullptr, qkv, NN, 384, DMM);
        // edge attention + aggregation + residual + LN
        agg_kernel<<<(NN + 7) / 8, 256>>>(edge_attr, edge_idx,
                                          eW1 + l * 48, eb1 + l * 16,
                                          eW2 + l * 16 * 128, eb2 + l * 128,
                                          ln_g + l * 128, ln_b + l * 128);
        // FFN
        sgemm_kernel<true><<<dim3(4, gRows), 256>>>(
            x, fW1 + (size_t)l * DMM * FFD, fb1 + l * FFD, h1, NN, FFD, DMM);
        sgemm_kernel<false><<<dim3(1, gRows), 256>>>(
            h1, fW2 + (size_t)l * FFD * DMM, fb2 + l * DMM, h2, NN, DMM, FFD);
        // residual + LN (last layer writes straight to d_out)
        float* outp = (l == LLN - 1) ? (float*)d_out : x;
        resln_kernel<<<(NN + 7) / 8, 256>>>(ln_g + l * 128, ln_b + l * 128, outp, x);
    }
    (void)in_sizes; (void)n_in; (void)out_size;
}

// round 2
// speedup vs baseline: 3.1258x; 3.1258x over previous
#include <cuda_runtime.h>
#include <cuda_bf16.h>
#include <cstdint>

#define NN 50000
#define EE 800000
#define DMM 128
#define LLN 6
#define FFD 512
#define EPSV 1e-5f

typedef __nv_bfloat16 bf16;
typedef __nv_bfloat162 bf162;

// ---------------- device-global scratch (no allocs allowed) ----------------
__device__ float g_x[NN * DMM];           // node features fp32 (current)
__device__ bf16  g_xh[NN * DMM];          // x split hi
__device__ bf16  g_xl[NN * DMM];          // x split lo
__device__ float g_qkv[NN * 3 * DMM];     // packed [q|k|v] per node (fp32)
__device__ bf16  g_h1h[NN * FFD];         // FFN hidden hi
__device__ bf16  g_h1l[NN * FFD];         // FFN hidden lo
__device__ float g_h2[NN * DMM];          // FFN out fp32
// weights, transposed [n][k], split hi/lo
__device__ bf16 g_Wqkvh[LLN * 384 * 128];
__device__ bf16 g_Wqkvl[LLN * 384 * 128];
__device__ bf16 g_W1h[LLN * 512 * 128];
__device__ bf16 g_W1l[LLN * 512 * 128];
__device__ bf16 g_W2h[LLN * 128 * 512];
__device__ bf16 g_W2l[LLN * 128 * 512];
__device__ int  g_deg[NN];
__device__ int  g_off[NN + 1];
__device__ int  g_cur[NN];
__device__ int  g_eid[EE];

__device__ __forceinline__ void splitf(float v, bf16& h, bf16& l) {
    h = __float2bfloat16(v);
    l = __float2bfloat16(v - __bfloat162float(h));
}

// ---------------- weight convert/transpose/split (+ zero g_deg) ----------------
// Wqkv_t [l][384][128], W1_t [l][512][128], W2_t [l][128][512]
__global__ void convw_kernel(const float* __restrict__ Wq, const float* __restrict__ Wk,
                             const float* __restrict__ Wv, const float* __restrict__ fW1,
                             const float* __restrict__ fW2) {
    const int S1 = 384 * 128, S2 = 512 * 128, S3 = 128 * 512;
    const int PER = S1 + S2 + S3;
    int idx = blockIdx.x * 256 + threadIdx.x;
    if (idx < NN) g_deg[idx] = 0;
    if (idx >= LLN * PER) return;
    int l = idx / PER;
    int rem = idx % PER;
    float v;
    bf16 *dh, *dl;
    if (rem < S1) {
        int n = rem / 128, k = rem % 128;
        if (n < 128)      v = Wq[(l * 128 + k) * 128 + n];
        else if (n < 256) v = Wk[(l * 128 + k) * 128 + (n - 128)];
        else              v = Wv[(l * 128 + k) * 128 + (n - 256)];
        dh = &g_Wqkvh[l * S1 + rem]; dl = &g_Wqkvl[l * S1 + rem];
    } else if (rem < S1 + S2) {
        int r2 = rem - S1;
        int n = r2 / 128, k = r2 % 128;
        v = fW1[(l * 128 + k) * 512 + n];
        dh = &g_W1h[l * S2 + r2]; dl = &g_W1l[l * S2 + r2];
    } else {
        int r3 = rem - S1 - S2;
        int n = r3 / 512, k = r3 % 512;
        v = fW2[(l * 512 + k) * 128 + n];
        dh = &g_W2h[l * S3 + r3]; dl = &g_W2l[l * S3 + r3];
    }
    bf16 h, lo;
    splitf(v, h, lo);
    *dh = h; *dl = lo;
}

// ---------------- CSR build ----------------
__global__ void count_kernel(const int* __restrict__ ei) {
    int e = blockIdx.x * 256 + threadIdx.x;
    if (e < EE) atomicAdd(&g_deg[ei[EE + e]], 1);
}

__global__ void scan_kernel() {
    __shared__ int sh[1024];
    int tid = threadIdx.x;
    int running = 0;
    for (int base = 0; base < NN; base += 1024) {
        int i = base + tid;
        int v = (i < NN) ? g_deg[i] : 0;
        sh[tid] = v;
        __syncthreads();
        for (int s = 1; s < 1024; s <<= 1) {
            int t = (tid >= s) ? sh[tid - s] : 0;
            __syncthreads();
            sh[tid] += t;
            __syncthreads();
        }
        int incl = sh[tid];
        if (i < NN) {
            int ex = running + incl - v;
            g_off[i] = ex;
            g_cur[i] = ex;
        }
        int tot = sh[1023];
        __syncthreads();
        running += tot;
    }
    if (tid == 0) g_off[NN] = running;
}

__global__ void fill_kernel(const int* __restrict__ ei) {
    int e = blockIdx.x * 256 + threadIdx.x;
    if (e < EE) {
        int d = ei[EE + e];
        int p = atomicAdd(&g_cur[d], 1);
        g_eid[p] = e;
    }
}

// ---------------- embedding ----------------
__global__ void embed_kernel(const float* __restrict__ nf, const float* __restrict__ W,
                             const float* __restrict__ b) {
    __shared__ float s[20];
    int node = blockIdx.x;
    int c = threadIdx.x;
    if (c < 20) s[c] = nf[node * 20 + c];
    __syncthreads();
    float acc = b[c];
#pragma unroll
    for (int k = 0; k < 20; k++) acc += s[k] * W[k * DMM + c];
    g_x[node * DMM + c] = acc;
    bf16 h, lo;
    splitf(acc, h, lo);
    g_xh[node * DMM + c] = h;
    g_xl[node * DMM + c] = lo;
}

// ---------------- bf16x3 tensor-core GEMM ----------------
// C[M,N] = act(A[M,K] @ B^T[N,K] + bias), A/B given as hi+lo bf16 pairs.
// BM=128 BN=128 BK=32, 256 threads = 8 warps in 2(M)x4(N).
__device__ __forceinline__ void mma16816(float* c, const uint32_t* a, const uint32_t* b) {
    asm volatile(
        "mma.sync.aligned.m16n8k16.row.col.f32.bf16.bf16.f32 "
        "{%0,%1,%2,%3},{%4,%5,%6,%7},{%8,%9},{%0,%1,%2,%3};\n"
        : "+f"(c[0]), "+f"(c[1]), "+f"(c[2]), "+f"(c[3])
        : "r"(a[0]), "r"(a[1]), "r"(a[2]), "r"(a[3]), "r"(b[0]), "r"(b[1]));
}

template <bool RELU, bool HILO>
__global__ __launch_bounds__(256) void mmgemm_kernel(
    const bf16* __restrict__ Ah, const bf16* __restrict__ Al,
    const bf16* __restrict__ Bh, const bf16* __restrict__ Bl,
    const float* __restrict__ bias,
    float* __restrict__ Cf, bf16* __restrict__ Ch, bf16* __restrict__ Cl,
    int M, int N, int K) {
    const int LDS = 40;
    __shared__ __align__(16) bf16 sAh[128][LDS];
    __shared__ __align__(16) bf16 sAl[128][LDS];
    __shared__ __align__(16) bf16 sBh[128][LDS];
    __shared__ __align__(16) bf16 sBl[128][LDS];

    int tid = threadIdx.x;
    int warp = tid >> 5, lane = tid & 31;
    int wm = warp >> 2, wn = warp & 3;
    int mBase = blockIdx.y * 128;
    int nBase = blockIdx.x * 128;

    float acc[4][4][4];
#pragma unroll
    for (int a = 0; a < 4; a++)
#pragma unroll
        for (int b = 0; b < 4; b++)
#pragma unroll
            for (int c = 0; c < 4; c++) acc[a][b][c] = 0.f;

    const int lr = lane >> 2;        // 0..7
    const int lc2 = (lane & 3) * 2;  // 0,2,4,6

    for (int k0 = 0; k0 < K; k0 += 32) {
#pragma unroll
        for (int it = 0; it < 2; it++) {
            int idx = tid + it * 256;
            int row = idx >> 2;
            int seg = (idx & 3) * 8;
            size_t gr = (size_t)(mBase + row);
            int4 vah, val;
            if ((int)gr < M) {
                vah = *(const int4*)(Ah + gr * K + k0 + seg);
                val = *(const int4*)(Al + gr * K + k0 + seg);
            } else {
                vah = make_int4(0, 0, 0, 0);
                val = vah;
            }
            *(int4*)(&sAh[row][seg]) = vah;
            *(int4*)(&sAl[row][seg]) = val;
            size_t gn = (size_t)(nBase + row);
            *(int4*)(&sBh[row][seg]) = *(const int4*)(Bh + gn * K + k0 + seg);
            *(int4*)(&sBl[row][seg]) = *(const int4*)(Bl + gn * K + k0 + seg);
        }
        __syncthreads();

#pragma unroll
        for (int ks = 0; ks < 2; ks++) {
            int kc = ks * 16 + lc2;
            uint32_t ah[4][4], al[4][4], bh[4][2], bl[4][2];
#pragma unroll
            for (int mt = 0; mt < 4; mt++) {
                int r = wm * 64 + mt * 16 + lr;
                ah[mt][0] = *(const uint32_t*)&sAh[r][kc];
                ah[mt][1] = *(const uint32_t*)&sAh[r + 8][kc];
                ah[mt][2] = *(const uint32_t*)&sAh[r][kc + 8];
                ah[mt][3] = *(const uint32_t*)&sAh[r + 8][kc + 8];
                al[mt][0] = *(const uint32_t*)&sAl[r][kc];
                al[mt][1] = *(const uint32_t*)&sAl[r + 8][kc];
                al[mt][2] = *(const uint32_t*)&sAl[r][kc + 8];
                al[mt][3] = *(const uint32_t*)&sAl[r + 8][kc + 8];
            }
#pragma unroll
            for (int nt = 0; nt < 4; nt++) {
                int n = wn * 32 + nt * 8 + lr;
                bh[nt][0] = *(const uint32_t*)&sBh[n][kc];
                bh[nt][1] = *(const uint32_t*)&sBh[n][kc + 8];
                bl[nt][0] = *(const uint32_t*)&sBl[n][kc];
                bl[nt][1] = *(const uint32_t*)&sBl[n][kc + 8];
            }
#pragma unroll
            for (int mt = 0; mt < 4; mt++)
#pragma unroll
                for (int nt = 0; nt < 4; nt++) {
                    mma16816(acc[mt][nt], ah[mt], bh[nt]);
                    mma16816(acc[mt][nt], ah[mt], bl[nt]);
                    mma16816(acc[mt][nt], al[mt], bh[nt]);
                }
        }
        __syncthreads();
    }

    // epilogue
#pragma unroll
    for (int mt = 0; mt < 4; mt++) {
        int r0 = mBase + wm * 64 + mt * 16 + lr;
        int r1 = r0 + 8;
#pragma unroll
        for (int nt = 0; nt < 4; nt++) {
            int c = nBase + wn * 32 + nt * 8 + lc2;
            float v00 = acc[mt][nt][0], v01 = acc[mt][nt][1];
            float v10 = acc[mt][nt][2], v11 = acc[mt][nt][3];
            if (bias != nullptr) {
                float b0 = bias[c], b1 = bias[c + 1];
                v00 += b0; v01 += b1; v10 += b0; v11 += b1;
            }
            if (RELU) {
                v00 = fmaxf(v00, 0.f); v01 = fmaxf(v01, 0.f);
                v10 = fmaxf(v10, 0.f); v11 = fmaxf(v11, 0.f);
            }
            if (HILO) {
                bf16 h0, l0, h1, l1;
                if (r0 < M) {
                    splitf(v00, h0, l0); splitf(v01, h1, l1);
                    *(bf162*)&Ch[(size_t)r0 * N + c] = bf162(h0, h1);
                    *(bf162*)&Cl[(size_t)r0 * N + c] = bf162(l0, l1);
                }
                if (r1 < M) {
                    splitf(v10, h0, l0); splitf(v11, h1, l1);
                    *(bf162*)&Ch[(size_t)r1 * N + c] = bf162(h0, h1);
                    *(bf162*)&Cl[(size_t)r1 * N + c] = bf162(l0, l1);
                }
            } else {
                if (r0 < M) *(float2*)&Cf[(size_t)r0 * N + c] = make_float2(v00, v01);
                if (r1 < M) *(float2*)&Cf[(size_t)r1 * N + c] = make_float2(v10, v11);
            }
        }
    }
}

// ---------------- edge attention + aggregation + residual + LN (warp per node) -------
// key identity: q.ee|head = hr . Z[.,head] + q.b2|head, Z[u][h]=sum_{d in h} W2[u][d] q[d]
__global__ __launch_bounds__(256) void agg_kernel(const float* __restrict__ edge_attr,
                                                  const int* __restrict__ edge_index,
                                                  const float* __restrict__ eW1,
                                                  const float* __restrict__ eb1,
                                                  const float* __restrict__ eW2,
                                                  const float* __restrict__ eb2,
                                                  const float* __restrict__ lg,
                                                  const float* __restrict__ lb) {
    __shared__ float sW1[48];
    __shared__ float sb1[16];
    __shared__ float sW2[16 * 128];
    __shared__ float sb2[128];
    __shared__ float sg[128];
    __shared__ float sb[128];
    int tid = threadIdx.x;
    if (tid < 48) sW1[tid] = eW1[tid];
    if (tid < 16) sb1[tid] = eb1[tid];
    for (int i = tid; i < 2048; i += 256) sW2[i] = eW2[i];
    if (tid < 128) {
        sb2[tid] = eb2[tid];
        sg[tid] = lg[tid];
        sb[tid] = lb[tid];
    }
    __syncthreads();

    int warp = tid / 32, lane = tid % 32;
    int node = blockIdx.x * 8 + warp;
    if (node >= NN) return;

    const int* srcArr = edge_index;  // row 0 = src
    int d0 = lane * 4;
    int head = lane >> 2;       // 0..7
    int i4 = lane & 3;          // 0..3
    int grp = lane & 28;

    float4 q = *(const float4*)&g_qkv[(size_t)node * 384 + d0];

    // per-node precompute: zq[uu] = Z[4*i4+uu][head]
    float zq[4] = {0.f, 0.f, 0.f, 0.f};
#pragma unroll
    for (int j = 0; j < 4; j++) {
        int jj = (i4 + j) & 3;
        int srcL = grp | jj;
        float q0 = __shfl_sync(0xffffffffu, q.x, srcL);
        float q1 = __shfl_sync(0xffffffffu, q.y, srcL);
        float q2 = __shfl_sync(0xffffffffu, q.z, srcL);
        float q3 = __shfl_sync(0xffffffffu, q.w, srcL);
        int col = head * 16 + jj * 4;
#pragma unroll
        for (int uu = 0; uu < 4; uu++) {
            const float* w = &sW2[(4 * i4 + uu) * 128 + col];
            zq[uu] += w[0] * q0 + w[1] * q1 + w[2] * q2 + w[3] * q3;
        }
    }
    float qb2 = q.x * sb2[d0] + q.y * sb2[d0 + 1] + q.z * sb2[d0 + 2] + q.w * sb2[d0 + 3];

    // per-lane edge-MLP weights for its 4 hidden units
    float w1a[4], w1b[4], w1c[4], w1d[4];
#pragma unroll
    for (int c = 0; c < 4; c++) {
        int u = 4 * i4 + c;
        w1a[c] = sW1[u]; w1b[c] = sW1[16 + u]; w1c[c] = sW1[32 + u]; w1d[c] = sb1[u];
    }

    float4 acc = make_float4(0.f, 0.f, 0.f, 0.f);
    int beg = g_off[node], end = g_off[node + 1];

    for (int t = beg; t < end; t++) {
        int e = g_eid[t];
        int j = srcArr[e];
        float ea0 = edge_attr[e * 3 + 0];
        float ea1 = edge_attr[e * 3 + 1];
        float ea2 = edge_attr[e * 3 + 2];
        float partial = qb2;
#pragma unroll
        for (int c = 0; c < 4; c++) {
            float h = fmaf(ea0, w1a[c], fmaf(ea1, w1b[c], fmaf(ea2, w1c[c], w1d[c])));
            partial = fmaf(fmaxf(h, 0.f), zq[c], partial);
        }
        float4 k4 = *(const float4*)&g_qkv[(size_t)j * 384 + 128 + d0];
        float p = partial + q.x * k4.x + q.y * k4.y + q.z * k4.z + q.w * k4.w;
        p += __shfl_xor_sync(0xffffffffu, p, 1);
        p += __shfl_xor_sync(0xffffffffu, p, 2);
        p *= 0.25f;  // 1/sqrt(16)
        float m = p;
        m = fmaxf(m, __shfl_xor_sync(0xffffffffu, m, 4));
        m = fmaxf(m, __shfl_xor_sync(0xffffffffu, m, 8));
        m = fmaxf(m, __shfl_xor_sync(0xffffffffu, m, 16));
        float ex = __expf(p - m);
        float sum = ex;
        sum += __shfl_xor_sync(0xffffffffu, sum, 4);
        sum += __shfl_xor_sync(0xffffffffu, sum, 8);
        sum += __shfl_xor_sync(0xffffffffu, sum, 16);
        float attn = ex / sum;
        float4 v4 = *(const float4*)&g_qkv[(size_t)j * 384 + 256 + d0];
        acc.x = fmaf(attn, v4.x, acc.x);
        acc.y = fmaf(attn, v4.y, acc.y);
        acc.z = fmaf(attn, v4.z, acc.z);
        acc.w = fmaf(attn, v4.w, acc.w);
    }

    // residual + LayerNorm
    float4 xr = *(const float4*)&g_x[(size_t)node * DMM + d0];
    float4 r;
    r.x = xr.x + acc.x; r.y = xr.y + acc.y;
    r.z = xr.z + acc.z; r.w = xr.w + acc.w;
    float s1 = r.x + r.y + r.z + r.w;
    float s2 = r.x * r.x + r.y * r.y + r.z * r.z + r.w * r.w;
#pragma unroll
    for (int s = 16; s >= 1; s >>= 1) {
        s1 += __shfl_xor_sync(0xffffffffu, s1, s);
        s2 += __shfl_xor_sync(0xffffffffu, s2, s);
    }
    float mu = s1 * (1.f / 128.f);
    float var = s2 * (1.f / 128.f) - mu * mu;
    float inv = rsqrtf(var + EPSV);
    float4 o;
    o.x = (r.x - mu) * inv * sg[d0 + 0] + sb[d0 + 0];
    o.y = (r.y - mu) * inv * sg[d0 + 1] + sb[d0 + 1];
    o.z = (r.z - mu) * inv * sg[d0 + 2] + sb[d0 + 2];
    o.w = (r.w - mu) * inv * sg[d0 + 3] + sb[d0 + 3];
    *(float4*)&g_x[(size_t)node * DMM + d0] = o;
    bf16 h0, l0, h1, l1;
    splitf(o.x, h0, l0); splitf(o.y, h1, l1);
    *(bf162*)&g_xh[(size_t)node * DMM + d0] = bf162(h0, h1);
    *(bf162*)&g_xl[(size_t)node * DMM + d0] = bf162(l0, l1);
    splitf(o.z, h0, l0); splitf(o.w, h1, l1);
    *(bf162*)&g_xh[(size_t)node * DMM + d0 + 2] = bf162(h0, h1);
    *(bf162*)&g_xl[(size_t)node * DMM + d0 + 2] = bf162(l0, l1);
}

// ---------------- FFN residual + LN (warp per node) ----------------
__global__ __launch_bounds__(256) void resln_kernel(const float* __restrict__ lg,
                                                    const float* __restrict__ lb,
                                                    float* __restrict__ out) {
    int tid = threadIdx.x;
    int warp = tid / 32, lane = tid % 32;
    int node = blockIdx.x * 8 + warp;
    if (node >= NN) return;
    int d0 = lane * 4;
    float4 a = *(const float4*)&g_x[(size_t)node * DMM + d0];
    float4 h = *(const float4*)&g_h2[(size_t)node * DMM + d0];
    float4 r;
    r.x = a.x + h.x; r.y = a.y + h.y; r.z = a.z + h.z; r.w = a.w + h.w;
    float s1 = r.x + r.y + r.z + r.w;
    float s2 = r.x * r.x + r.y * r.y + r.z * r.z + r.w * r.w;
#pragma unroll
    for (int s = 16; s >= 1; s >>= 1) {
        s1 += __shfl_xor_sync(0xffffffffu, s1, s);
        s2 += __shfl_xor_sync(0xffffffffu, s2, s);
    }
    float mu = s1 * (1.f / 128.f);
    float var = s2 * (1.f / 128.f) - mu * mu;
    float inv = rsqrtf(var + EPSV);
    float4 g4 = *(const float4*)&lg[d0];
    float4 b4 = *(const float4*)&lb[d0];
    float4 o;
    o.x = (r.x - mu) * inv * g4.x + b4.x;
    o.y = (r.y - mu) * inv * g4.y + b4.y;
    o.z = (r.z - mu) * inv * g4.z + b4.z;
    o.w = (r.w - mu) * inv * g4.w + b4.w;
    *(float4*)&out[(size_t)node * DMM + d0] = o;
    if (out != (float*)g_x) *(float4*)&g_x[(size_t)node * DMM + d0] = o;
    bf16 h0, l0, h1, l1;
    splitf(o.x, h0, l0); splitf(o.y, h1, l1);
    *(bf162*)&g_xh[(size_t)node * DMM + d0] = bf162(h0, h1);
    *(bf162*)&g_xl[(size_t)node * DMM + d0] = bf162(l0, l1);
    splitf(o.z, h0, l0); splitf(o.w, h1, l1);
    *(bf162*)&g_xh[(size_t)node * DMM + d0 + 2] = bf162(h0, h1);
    *(bf162*)&g_xl[(size_t)node * DMM + d0 + 2] = bf162(l0, l1);
}

// ---------------- launch ----------------
extern "C" void kernel_launch(void* const* d_in, const int* in_sizes, int n_in,
                              void* d_out, int out_size) {
    const float* nf        = (const float*)d_in[0];
    const float* edge_attr = (const float*)d_in[1];
    const int*   edge_idx  = (const int*)d_in[2];
    const float* emb_W     = (const float*)d_in[3];
    const float* emb_b     = (const float*)d_in[4];
    const float* Wq        = (const float*)d_in[5];
    const float* Wk        = (const float*)d_in[6];
    const float* Wv        = (const float*)d_in[7];
    const float* eW1       = (const float*)d_in[8];
    const float* eb1       = (const float*)d_in[9];
    const float* eW2       = (const float*)d_in[10];
    const float* eb2       = (const float*)d_in[11];
    const float* ln_g      = (const float*)d_in[12];
    const float* ln_b      = (const float*)d_in[13];
    const float* fW1       = (const float*)d_in[14];
    const float* fb1       = (const float*)d_in[15];
    const float* fW2       = (const float*)d_in[16];
    const float* fb2       = (const float*)d_in[17];

    float *x, *qkv, *h2;
    bf16 *xh, *xl, *h1h, *h1l, *wqh, *wql, *w1h, *w1l, *w2h, *w2l;
    cudaGetSymbolAddress((void**)&x, g_x);
    cudaGetSymbolAddress((void**)&qkv, g_qkv);
    cudaGetSymbolAddress((void**)&h2, g_h2);
    cudaGetSymbolAddress((void**)&xh, g_xh);
    cudaGetSymbolAddress((void**)&xl, g_xl);
    cudaGetSymbolAddress((void**)&h1h, g_h1h);
    cudaGetSymbolAddress((void**)&h1l, g_h1l);
    cudaGetSymbolAddress((void**)&wqh, g_Wqkvh);
    cudaGetSymbolAddress((void**)&wql, g_Wqkvl);
    cudaGetSymbolAddress((void**)&w1h, g_W1h);
    cudaGetSymbolAddress((void**)&w1l, g_W1l);
    cudaGetSymbolAddress((void**)&w2h, g_W2h);
    cudaGetSymbolAddress((void**)&w2l, g_W2l);

    // weight convert (+ zero deg)
    {
        const int TOT = LLN * (384 * 128 + 512 * 128 + 128 * 512);
        convw_kernel<<<(TOT + 255) / 256, 256>>>(Wq, Wk, Wv, fW1, fW2);
    }
    // CSR build (by dst)
    count_kernel<<<(EE + 255) / 256, 256>>>(edge_idx);
    scan_kernel<<<1, 1024>>>();
    fill_kernel<<<(EE + 255) / 256, 256>>>(edge_idx);
    // embedding
    embed_kernel<<<NN, 128>>>(nf, emb_W, emb_b);

    const int gRows = (NN + 127) / 128;  // 391
    for (int l = 0; l < LLN; l++) {
        // QKV: [N,128] @ [128,384] -> qkv fp32
        mmgemm_kernel<false, false><<<dim3(3, gRows), 256>>>(
            xh, xl, wqh + (size_t)l * 384 * 128, wql + (size_t)l * 384 * 128,
            nullptr, qkv, nullptr, nullptr, NN, 384, 128);
        // edge attention + aggregation + residual + LN (updates x, xh, xl)
        agg_kernel<<<(NN + 7) / 8, 256>>>(edge_attr, edge_idx,
                                          eW1 + l * 48, eb1 + l * 16,
                                          eW2 + l * 16 * 128, eb2 + l * 128,
                                          ln_g + l * 128, ln_b + l * 128);
        // FFN1: relu(x@W1 + b1) -> h1 hi/lo
        mmgemm_kernel<true, true><<<dim3(4, gRows), 256>>>(
            xh, xl, w1h + (size_t)l * 512 * 128, w1l + (size_t)l * 512 * 128,
            fb1 + l * 512, nullptr, h1h, h1l, NN, 512, 128);
        // FFN2: h1@W2 + b2 -> h2 fp32
        mmgemm_kernel<false, false><<<dim3(1, gRows), 256>>>(
            h1h, h1l, w2h + (size_t)l * 128 * 512, w2l + (size_t)l * 128 * 512,
            fb2 + l * 128, h2, nullptr, nullptr, NN, 128, 512);
        // residual + LN (last layer also writes d_out)
        float* outp = (l == LLN - 1) ? (float*)d_out : x;
        resln_kernel<<<(NN + 7) / 8, 256>>>(ln_g + l * 128, ln_b + l * 128, outp);
    }
    (void)in_sizes; (void)n_in; (void)out_size;
}

// round 3
// speedup vs baseline: 4.6205x; 1.4782x over previous
#include <cuda_runtime.h>
#include <cuda_fp16.h>
#include <cstdint>

#define NN 50000
#define EE 800000
#define DMM 128
#define LLN 6
#define FFD 512
#define EPSV 1e-5f

typedef __half half_t;

// ---------------- device-global scratch (no allocs allowed) ----------------
__device__ float  g_x[NN * DMM];          // node features fp32 (current)
__device__ half_t g_xh[NN * DMM];         // x as fp16 (GEMM operand)
__device__ float  g_qkv[NN * 3 * DMM];    // packed [q|k|v] per node (fp32)
__device__ half_t g_h1[NN * FFD];         // FFN hidden fp16
__device__ float  g_h2[NN * DMM];         // FFN out fp32
// weights, transposed [n][k], fp16
__device__ half_t g_Wqkv[LLN * 384 * 128];
__device__ half_t g_W1[LLN * 512 * 128];
__device__ half_t g_W2[LLN * 128 * 512];
__device__ int    g_deg[NN];
__device__ int    g_off[NN + 1];
__device__ int    g_cur[NN];
__device__ int    g_eid[EE];

// ---------------- weight convert/transpose (+ zero g_deg) ----------------
__global__ void convw_kernel(const float* __restrict__ Wq, const float* __restrict__ Wk,
                             const float* __restrict__ Wv, const float* __restrict__ fW1,
                             const float* __restrict__ fW2) {
    const int S1 = 384 * 128, S2 = 512 * 128, S3 = 128 * 512;
    const int PER = S1 + S2 + S3;
    int idx = blockIdx.x * 256 + threadIdx.x;
    if (idx < NN) g_deg[idx] = 0;
    if (idx >= LLN * PER) return;
    int l = idx / PER;
    int rem = idx % PER;
    float v;
    half_t* dst;
    if (rem < S1) {
        int n = rem / 128, k = rem % 128;
        if (n < 128)      v = Wq[(l * 128 + k) * 128 + n];
        else if (n < 256) v = Wk[(l * 128 + k) * 128 + (n - 128)];
        else              v = Wv[(l * 128 + k) * 128 + (n - 256)];
        dst = &g_Wqkv[l * S1 + rem];
    } else if (rem < S1 + S2) {
        int r2 = rem - S1;
        int n = r2 / 128, k = r2 % 128;
        v = fW1[(l * 128 + k) * 512 + n];
        dst = &g_W1[l * S2 + r2];
    } else {
        int r3 = rem - S1 - S2;
        int n = r3 / 512, k = r3 % 512;
        v = fW2[(l * 512 + k) * 128 + n];
        dst = &g_W2[l * S3 + r3];
    }
    *dst = __float2half_rn(v);
}

// ---------------- CSR build ----------------
__global__ void count_kernel(const int* __restrict__ ei) {
    int e = blockIdx.x * 256 + threadIdx.x;
    if (e < EE) atomicAdd(&g_deg[ei[EE + e]], 1);
}

__global__ void scan_kernel() {
    __shared__ int sh[1024];
    int tid = threadIdx.x;
    int running = 0;
    for (int base = 0; base < NN; base += 1024) {
        int i = base + tid;
        int v = (i < NN) ? g_deg[i] : 0;
        sh[tid] = v;
        __syncthreads();
        for (int s = 1; s < 1024; s <<= 1) {
            int t = (tid >= s) ? sh[tid - s] : 0;
            __syncthreads();
            sh[tid] += t;
            __syncthreads();
        }
        int incl = sh[tid];
        if (i < NN) {
            int ex = running + incl - v;
            g_off[i] = ex;
            g_cur[i] = ex;
        }
        int tot = sh[1023];
        __syncthreads();
        running += tot;
    }
    if (tid == 0) g_off[NN] = running;
}

__global__ void fill_kernel(const int* __restrict__ ei) {
    int e = blockIdx.x * 256 + threadIdx.x;
    if (e < EE) {
        int d = ei[EE + e];
        int p = atomicAdd(&g_cur[d], 1);
        g_eid[p] = e;
    }
}

// ---------------- embedding ----------------
__global__ void embed_kernel(const float* __restrict__ nf, const float* __restrict__ W,
                             const float* __restrict__ b) {
    __shared__ float s[20];
    int node = blockIdx.x;
    int c = threadIdx.x;
    if (c < 20) s[c] = nf[node * 20 + c];
    __syncthreads();
    float acc = b[c];
#pragma unroll
    for (int k = 0; k < 20; k++) acc += s[k] * W[k * DMM + c];
    g_x[node * DMM + c] = acc;
    g_xh[node * DMM + c] = __float2half_rn(acc);
}

// ---------------- fp16 tensor-core GEMM ----------------
// C[M,N] = act(A[M,K] @ B^T[N,K] + bias), fp32 accumulate.
// BM=128 BN=128 BK=64, 256 threads = 8 warps in 2(M)x4(N).
__device__ __forceinline__ void mma16816h(float* c, const uint32_t* a, const uint32_t* b) {
    asm volatile(
        "mma.sync.aligned.m16n8k16.row.col.f32.f16.f16.f32 "
        "{%0,%1,%2,%3},{%4,%5,%6,%7},{%8,%9},{%0,%1,%2,%3};\n"
        : "+f"(c[0]), "+f"(c[1]), "+f"(c[2]), "+f"(c[3])
        : "r"(a[0]), "r"(a[1]), "r"(a[2]), "r"(a[3]), "r"(b[0]), "r"(b[1]));
}

template <bool RELU, bool OUTF32>
__global__ __launch_bounds__(256) void hgemm_kernel(
    const half_t* __restrict__ A, const half_t* __restrict__ B,
    const float* __restrict__ bias,
    float* __restrict__ Cf, half_t* __restrict__ Ch,
    int M, int N, int K) {
    const int LDS = 72;  // 64 + 8 pad halves
    __shared__ __align__(16) half_t sA[128][LDS];
    __shared__ __align__(16) half_t sB[128][LDS];

    int tid = threadIdx.x;
    int warp = tid >> 5, lane = tid & 31;
    int wm = warp >> 2, wn = warp & 3;
    int mBase = blockIdx.y * 128;
    int nBase = blockIdx.x * 128;

    float acc[4][4][4];
#pragma unroll
    for (int a = 0; a < 4; a++)
#pragma unroll
        for (int b = 0; b < 4; b++)
#pragma unroll
            for (int c = 0; c < 4; c++) acc[a][b][c] = 0.f;

    const int lr = lane >> 2;
    const int lc2 = (lane & 3) * 2;

    for (int k0 = 0; k0 < K; k0 += 64) {
#pragma unroll
        for (int it = 0; it < 4; it++) {
            int idx = tid + it * 256;
            int row = idx >> 3;
            int seg = (idx & 7) * 8;
            int ar = mBase + row;
            ar = (ar < M) ? ar : (M - 1);  // clamp; OOB rows never stored
            *(int4*)&sA[row][seg] = *(const int4*)(A + (size_t)ar * K + k0 + seg);
            *(int4*)&sB[row][seg] = *(const int4*)(B + (size_t)(nBase + row) * K + k0 + seg);
        }
        __syncthreads();
#pragma unroll
        for (int ks = 0; ks < 4; ks++) {
            int kc = ks * 16 + lc2;
            uint32_t af[4][4], bf[4][2];
#pragma unroll
            for (int mt = 0; mt < 4; mt++) {
                int r = wm * 64 + mt * 16 + lr;
                af[mt][0] = *(const uint32_t*)&sA[r][kc];
                af[mt][1] = *(const uint32_t*)&sA[r + 8][kc];
                af[mt][2] = *(const uint32_t*)&sA[r][kc + 8];
                af[mt][3] = *(const uint32_t*)&sA[r + 8][kc + 8];
            }
#pragma unroll
            for (int nt = 0; nt < 4; nt++) {
                int n = wn * 32 + nt * 8 + lr;
                bf[nt][0] = *(const uint32_t*)&sB[n][kc];
                bf[nt][1] = *(const uint32_t*)&sB[n][kc + 8];
            }
#pragma unroll
            for (int mt = 0; mt < 4; mt++)
#pragma unroll
                for (int nt = 0; nt < 4; nt++) mma16816h(acc[mt][nt], af[mt], bf[nt]);
        }
        __syncthreads();
    }

#pragma unroll
    for (int mt = 0; mt < 4; mt++) {
        int r0 = mBase + wm * 64 + mt * 16 + lr;
        int r1 = r0 + 8;
#pragma unroll
        for (int nt = 0; nt < 4; nt++) {
            int c = nBase + wn * 32 + nt * 8 + lc2;
            float v00 = acc[mt][nt][0], v01 = acc[mt][nt][1];
            float v10 = acc[mt][nt][2], v11 = acc[mt][nt][3];
            if (bias != nullptr) {
                float b0 = bias[c], b1 = bias[c + 1];
                v00 += b0; v01 += b1; v10 += b0; v11 += b1;
            }
            if (RELU) {
                v00 = fmaxf(v00, 0.f); v01 = fmaxf(v01, 0.f);
                v10 = fmaxf(v10, 0.f); v11 = fmaxf(v11, 0.f);
            }
            if (OUTF32) {
                if (r0 < M) *(float2*)&Cf[(size_t)r0 * N + c] = make_float2(v00, v01);
                if (r1 < M) *(float2*)&Cf[(size_t)r1 * N + c] = make_float2(v10, v11);
            } else {
                if (r0 < M)
                    *(__half2*)&Ch[(size_t)r0 * N + c] =
                        __floats2half2_rn(v00, v01);
                if (r1 < M)
                    *(__half2*)&Ch[(size_t)r1 * N + c] =
                        __floats2half2_rn(v10, v11);
            }
        }
    }
}

// ---------------- edge attention + aggregation + residual + LN (warp per node) -------
// identity: q.ee|head = hr . Z[.,head] + q.b2|head, Z[u][h]=sum_{d in h} W2[u][d] q[d]
__global__ __launch_bounds__(256) void agg_kernel(const float* __restrict__ edge_attr,
                                                  const int* __restrict__ edge_index,
                                                  const float* __restrict__ eW1,
                                                  const float* __restrict__ eb1,
                                                  const float* __restrict__ eW2,
                                                  const float* __restrict__ eb2,
                                                  const float* __restrict__ lg,
                                                  const float* __restrict__ lb) {
    __shared__ float sW1[48];
    __shared__ float sb1[16];
    __shared__ float sW2[16 * 128];
    __shared__ float sb2[128];
    __shared__ float sg[128];
    __shared__ float sb[128];
    int tid = threadIdx.x;
    if (tid < 48) sW1[tid] = eW1[tid];
    if (tid < 16) sb1[tid] = eb1[tid];
    for (int i = tid; i < 2048; i += 256) sW2[i] = eW2[i];
    if (tid < 128) {
        sb2[tid] = eb2[tid];
        sg[tid] = lg[tid];
        sb[tid] = lb[tid];
    }
    __syncthreads();

    int warp = tid / 32, lane = tid % 32;
    int node = blockIdx.x * 8 + warp;
    if (node >= NN) return;

    const int* srcArr = edge_index;  // row 0 = src
    int d0 = lane * 4;
    int head = lane >> 2;
    int i4 = lane & 3;
    int grp = lane & 28;

    float4 q = *(const float4*)&g_qkv[(size_t)node * 384 + d0];

    // per-node precompute: zq[uu] = Z[4*i4+uu][head]
    float zq[4] = {0.f, 0.f, 0.f, 0.f};
#pragma unroll
    for (int j = 0; j < 4; j++) {
        int jj = (i4 + j) & 3;
        int srcL = grp | jj;
        float q0 = __shfl_sync(0xffffffffu, q.x, srcL);
        float q1 = __shfl_sync(0xffffffffu, q.y, srcL);
        float q2 = __shfl_sync(0xffffffffu, q.z, srcL);
        float q3 = __shfl_sync(0xffffffffu, q.w, srcL);
        int col = head * 16 + jj * 4;
#pragma unroll
        for (int uu = 0; uu < 4; uu++) {
            const float* w = &sW2[(4 * i4 + uu) * 128 + col];
            zq[uu] += w[0] * q0 + w[1] * q1 + w[2] * q2 + w[3] * q3;
        }
    }
    float qb2 = q.x * sb2[d0] + q.y * sb2[d0 + 1] + q.z * sb2[d0 + 2] + q.w * sb2[d0 + 3];

    float w1a[4], w1b[4], w1c[4], w1d[4];
#pragma unroll
    for (int c = 0; c < 4; c++) {
        int u = 4 * i4 + c;
        w1a[c] = sW1[u]; w1b[c] = sW1[16 + u]; w1c[c] = sW1[32 + u]; w1d[c] = sb1[u];
    }

    float4 acc = make_float4(0.f, 0.f, 0.f, 0.f);
    int beg = g_off[node], end = g_off[node + 1];

    for (int t = beg; t < end; t++) {
        int e = g_eid[t];
        int j = srcArr[e];
        float ea0 = edge_attr[e * 3 + 0];
        float ea1 = edge_attr[e * 3 + 1];
        float ea2 = edge_attr[e * 3 + 2];
        float partial = qb2;
#pragma unroll
        for (int c = 0; c < 4; c++) {
            float h = fmaf(ea0, w1a[c], fmaf(ea1, w1b[c], fmaf(ea2, w1c[c], w1d[c])));
            partial = fmaf(fmaxf(h, 0.f), zq[c], partial);
        }
        float4 k4 = *(const float4*)&g_qkv[(size_t)j * 384 + 128 + d0];
        float p = partial + q.x * k4.x + q.y * k4.y + q.z * k4.z + q.w * k4.w;
        p += __shfl_xor_sync(0xffffffffu, p, 1);
        p += __shfl_xor_sync(0xffffffffu, p, 2);
        // logits are O(1) here; exp without max-subtraction is safe
        float ex = __expf(p * 0.25f);
        float sum = ex;
        sum += __shfl_xor_sync(0xffffffffu, sum, 4);
        sum += __shfl_xor_sync(0xffffffffu, sum, 8);
        sum += __shfl_xor_sync(0xffffffffu, sum, 16);
        float attn = ex / sum;
        float4 v4 = *(const float4*)&g_qkv[(size_t)j * 384 + 256 + d0];
        acc.x = fmaf(attn, v4.x, acc.x);
        acc.y = fmaf(attn, v4.y, acc.y);
        acc.z = fmaf(attn, v4.z, acc.z);
        acc.w = fmaf(attn, v4.w, acc.w);
    }

    // residual + LayerNorm
    float4 xr = *(const float4*)&g_x[(size_t)node * DMM + d0];
    float4 r;
    r.x = xr.x + acc.x; r.y = xr.y + acc.y;
    r.z = xr.z + acc.z; r.w = xr.w + acc.w;
    float s1 = r.x + r.y + r.z + r.w;
    float s2 = r.x * r.x + r.y * r.y + r.z * r.z + r.w * r.w;
#pragma unroll
    for (int s = 16; s >= 1; s >>= 1) {
        s1 += __shfl_xor_sync(0xffffffffu, s1, s);
        s2 += __shfl_xor_sync(0xffffffffu, s2, s);
    }
    float mu = s1 * (1.f / 128.f);
    float var = s2 * (1.f / 128.f) - mu * mu;
    float inv = rsqrtf(var + EPSV);
    float4 o;
    o.x = (r.x - mu) * inv * sg[d0 + 0] + sb[d0 + 0];
    o.y = (r.y - mu) * inv * sg[d0 + 1] + sb[d0 + 1];
    o.z = (r.z - mu) * inv * sg[d0 + 2] + sb[d0 + 2];
    o.w = (r.w - mu) * inv * sg[d0 + 3] + sb[d0 + 3];
    *(float4*)&g_x[(size_t)node * DMM + d0] = o;
    *(__half2*)&g_xh[(size_t)node * DMM + d0] = __floats2half2_rn(o.x, o.y);
    *(__half2*)&g_xh[(size_t)node * DMM + d0 + 2] = __floats2half2_rn(o.z, o.w);
}

// ---------------- FFN residual + LN (warp per node) ----------------
__global__ __launch_bounds__(256) void resln_kernel(const float* __restrict__ lg,
                                                    const float* __restrict__ lb,
                                                    float* __restrict__ out) {
    int tid = threadIdx.x;
    int warp = tid / 32, lane = tid % 32;
    int node = blockIdx.x * 8 + warp;
    if (node >= NN) return;
    int d0 = lane * 4;
    float4 a = *(const float4*)&g_x[(size_t)node * DMM + d0];
    float4 h = *(const float4*)&g_h2[(size_t)node * DMM + d0];
    float4 r;
    r.x = a.x + h.x; r.y = a.y + h.y; r.z = a.z + h.z; r.w = a.w + h.w;
    float s1 = r.x + r.y + r.z + r.w;
    float s2 = r.x * r.x + r.y * r.y + r.z * r.z + r.w * r.w;
#pragma unroll
    for (int s = 16; s >= 1; s >>= 1) {
        s1 += __shfl_xor_sync(0xffffffffu, s1, s);
        s2 += __shfl_xor_sync(0xffffffffu, s2, s);
    }
    float mu = s1 * (1.f / 128.f);
    float var = s2 * (1.f / 128.f) - mu * mu;
    float inv = rsqrtf(var + EPSV);
    float4 g4 = *(const float4*)&lg[d0];
    float4 b4 = *(const float4*)&lb[d0];
    float4 o;
    o.x = (r.x - mu) * inv * g4.x + b4.x;
    o.y = (r.y - mu) * inv * g4.y + b4.y;
    o.z = (r.z - mu) * inv * g4.z + b4.z;
    o.w = (r.w - mu) * inv * g4.w + b4.w;
    *(float4*)&out[(size_t)node * DMM + d0] = o;
    if (out != (float*)g_x) *(float4*)&g_x[(size_t)node * DMM + d0] = o;
    *(__half2*)&g_xh[(size_t)node * DMM + d0] = __floats2half2_rn(o.x, o.y);
    *(__half2*)&g_xh[(size_t)node * DMM + d0 + 2] = __floats2half2_rn(o.z, o.w);
}

// ---------------- launch ----------------
extern "C" void kernel_launch(void* const* d_in, const int* in_sizes, int n_in,
                              void* d_out, int out_size) {
    const float* nf        = (const float*)d_in[0];
    const float* edge_attr = (const float*)d_in[1];
    const int*   edge_idx  = (const int*)d_in[2];
    const float* emb_W     = (const float*)d_in[3];
    const float* emb_b     = (const float*)d_in[4];
    const float* Wq        = (const float*)d_in[5];
    const float* Wk        = (const float*)d_in[6];
    const float* Wv        = (const float*)d_in[7];
    const float* eW1       = (const float*)d_in[8];
    const float* eb1       = (const float*)d_in[9];
    const float* eW2       = (const float*)d_in[10];
    const float* eb2       = (const float*)d_in[11];
    const float* ln_g      = (const float*)d_in[12];
    const float* ln_b      = (const float*)d_in[13];
    const float* fW1       = (const float*)d_in[14];
    const float* fb1       = (const float*)d_in[15];
    const float* fW2       = (const float*)d_in[16];
    const float* fb2       = (const float*)d_in[17];

    float *x, *qkv, *h2;
    half_t *xh, *h1, *wq, *w1, *w2;
    cudaGetSymbolAddress((void**)&x, g_x);
    cudaGetSymbolAddress((void**)&qkv, g_qkv);
    cudaGetSymbolAddress((void**)&h2, g_h2);
    cudaGetSymbolAddress((void**)&xh, g_xh);
    cudaGetSymbolAddress((void**)&h1, g_h1);
    cudaGetSymbolAddress((void**)&wq, g_Wqkv);
    cudaGetSymbolAddress((void**)&w1, g_W1);
    cudaGetSymbolAddress((void**)&w2, g_W2);

    {
        const int TOT = LLN * (384 * 128 + 512 * 128 + 128 * 512);
        convw_kernel<<<(TOT + 255) / 256, 256>>>(Wq, Wk, Wv, fW1, fW2);
    }
    count_kernel<<<(EE + 255) / 256, 256>>>(edge_idx);
    scan_kernel<<<1, 1024>>>();
    fill_kernel<<<(EE + 255) / 256, 256>>>(edge_idx);
    embed_kernel<<<NN, 128>>>(nf, emb_W, emb_b);

    const int gRows = (NN + 127) / 128;  // 391
    for (int l = 0; l < LLN; l++) {
        // QKV: [N,128] @ [128,384] -> qkv fp32
        hgemm_kernel<false, true><<<dim3(3, gRows), 256>>>(
            xh, wq + (size_t)l * 384 * 128, nullptr, qkv, nullptr, NN, 384, 128);
        // edge attention + aggregation + residual + LN (updates x, xh)
        agg_kernel<<<(NN + 7) / 8, 256>>>(edge_attr, edge_idx,
                                          eW1 + l * 48, eb1 + l * 16,
                                          eW2 + l * 16 * 128, eb2 + l * 128,
                                          ln_g + l * 128, ln_b + l * 128);
        // FFN1: relu(x@W1 + b1) -> h1 fp16
        hgemm_kernel<true, false><<<dim3(4, gRows), 256>>>(
            xh, w1 + (size_t)l * 512 * 128, fb1 + l * 512, nullptr, h1, NN, 512, 128);
        // FFN2: h1@W2 + b2 -> h2 fp32
        hgemm_kernel<false, true><<<dim3(1, gRows), 256>>>(
            h1, w2 + (size_t)l * 128 * 512, fb2 + l * 128, h2, nullptr, NN, 128, 512);
        // residual + LN (last layer also writes d_out)
        float* outp = (l == LLN - 1) ? (float*)d_out : x;
        resln_kernel<<<(NN + 7) / 8, 256>>>(ln_g + l * 128, ln_b + l * 128, outp);
    }
    (void)in_sizes; (void)n_in; (void)out_size;
}

// round 4
// speedup vs baseline: 5.7807x; 1.2511x over previous
#include <cuda_runtime.h>
#include <cuda_fp16.h>
#include <cstdint>

#define NN 50000
#define EE 800000
#define DMM 128
#define LLN 6
#define FFD 512
#define EPSV 1e-5f

typedef __half half_t;

// ---------------- device-global scratch ----------------
__device__ float  g_x[NN * DMM];      // node features fp32
__device__ half_t g_xh[NN * DMM];     // x fp16 (GEMM operand)
__device__ float  g_q[NN * DMM];      // q fp32
__device__ half_t g_kh[NN * DMM];     // k fp16
__device__ float  g_v[NN * DMM];      // v fp32
__device__ half_t g_h1[NN * FFD];     // FFN hidden fp16
__device__ half_t g_Wqkv[LLN * 384 * 128];
__device__ half_t g_W1[LLN * 512 * 128];
__device__ half_t g_W2[LLN * 128 * 512];
__device__ int    g_deg[NN];
__device__ int    g_off[NN + 1];
__device__ int    g_cur[NN];
__device__ float4 g_es[EE];           // per-CSR-slot: (src_as_float, ea0, ea1, ea2)

// ---------------- cp.async helpers ----------------
__device__ __forceinline__ void cpa16(void* smem, const void* gmem) {
    uint32_t s = (uint32_t)__cvta_generic_to_shared(smem);
    asm volatile("cp.async.cg.shared.global [%0], [%1], 16;" ::"r"(s), "l"(gmem));
}
__device__ __forceinline__ void cpa_commit() { asm volatile("cp.async.commit_group;"); }

// ---------------- weight convert/transpose (+ zero g_deg) ----------------
__global__ void convw_kernel(const float* __restrict__ Wq, const float* __restrict__ Wk,
                             const float* __restrict__ Wv, const float* __restrict__ fW1,
                             const float* __restrict__ fW2) {
    const int S1 = 384 * 128, S2 = 512 * 128, S3 = 128 * 512;
    const int PER = S1 + S2 + S3;
    int idx = blockIdx.x * 256 + threadIdx.x;
    if (idx < NN) g_deg[idx] = 0;
    if (idx >= LLN * PER) return;
    int l = idx / PER;
    int rem = idx % PER;
    float v;
    half_t* dst;
    if (rem < S1) {
        int n = rem / 128, k = rem % 128;
        if (n < 128)      v = Wq[(l * 128 + k) * 128 + n];
        else if (n < 256) v = Wk[(l * 128 + k) * 128 + (n - 128)];
        else              v = Wv[(l * 128 + k) * 128 + (n - 256)];
        dst = &g_Wqkv[l * S1 + rem];
    } else if (rem < S1 + S2) {
        int r2 = rem - S1;
        int n = r2 / 128, k = r2 % 128;
        v = fW1[(l * 128 + k) * 512 + n];
        dst = &g_W1[l * S2 + r2];
    } else {
        int r3 = rem - S1 - S2;
        int n = r3 / 512, k = r3 % 512;
        v = fW2[(l * 512 + k) * 128 + n];
        dst = &g_W2[l * S3 + r3];
    }
    *dst = __float2half_rn(v);
}

// ---------------- CSR build ----------------
__global__ void count_kernel(const int* __restrict__ ei) {
    int e = blockIdx.x * 256 + threadIdx.x;
    if (e < EE) atomicAdd(&g_deg[ei[EE + e]], 1);
}

__global__ void scan_kernel() {
    __shared__ int sh[1024];
    int tid = threadIdx.x;
    int running = 0;
    for (int base = 0; base < NN; base += 1024) {
        int i = base + tid;
        int v = (i < NN) ? g_deg[i] : 0;
        sh[tid] = v;
        __syncthreads();
        for (int s = 1; s < 1024; s <<= 1) {
            int t = (tid >= s) ? sh[tid - s] : 0;
            __syncthreads();
            sh[tid] += t;
            __syncthreads();
        }
        int incl = sh[tid];
        if (i < NN) {
            int ex = running + incl - v;
            g_off[i] = ex;
            g_cur[i] = ex;
        }
        int tot = sh[1023];
        __syncthreads();
        running += tot;
    }
    if (tid == 0) g_off[NN] = running;
}

// fill CSR slots with streamed (src, edge_attr) records
__global__ void fill_kernel(const int* __restrict__ ei, const float* __restrict__ ea) {
    int e = blockIdx.x * 256 + threadIdx.x;
    if (e < EE) {
        int d = ei[EE + e];
        int s = ei[e];
        int p = atomicAdd(&g_cur[d], 1);
        g_es[p] = make_float4(__int_as_float(s), ea[e * 3], ea[e * 3 + 1], ea[e * 3 + 2]);
    }
}

// ---------------- embedding ----------------
__global__ void embed_kernel(const float* __restrict__ nf, const float* __restrict__ W,
                             const float* __restrict__ b) {
    __shared__ float s[20];
    int node = blockIdx.x;
    int c = threadIdx.x;
    if (c < 20) s[c] = nf[node * 20 + c];
    __syncthreads();
    float acc = b[c];
#pragma unroll
    for (int k = 0; k < 20; k++) acc += s[k] * W[k * DMM + c];
    g_x[node * DMM + c] = acc;
    g_xh[node * DMM + c] = __float2half_rn(acc);
}

// ---------------- fp16 tensor-core GEMM (cp.async 2-stage) ----------------
// MODE 0: QKV split epilogue (q f32 / k f16 / v f32, no bias)
// MODE 1: bias + relu, half out (FFN1)
// MODE 2: bias + fused residual + LayerNorm (FFN2), N must be 128
__device__ __forceinline__ void mma16816h(float* c, const uint32_t* a, const uint32_t* b) {
    asm volatile(
        "mma.sync.aligned.m16n8k16.row.col.f32.f16.f16.f32 "
        "{%0,%1,%2,%3},{%4,%5,%6,%7},{%8,%9},{%0,%1,%2,%3};\n"
        : "+f"(c[0]), "+f"(c[1]), "+f"(c[2]), "+f"(c[3])
        : "r"(a[0]), "r"(a[1]), "r"(a[2]), "r"(a[3]), "r"(b[0]), "r"(b[1]));
}

#define LDSH 72
#define ASZ (128 * LDSH)             // halves per stage per array
#define SMEMSZ (4 * ASZ * 2 + 4096)  // 2 stages x (A,B) + 2 reduction arrays

template <int MODE>
__global__ __launch_bounds__(256) void hgemm_kernel(
    const half_t* __restrict__ A, const half_t* __restrict__ B,
    const float* __restrict__ bias,
    float* __restrict__ q_out, half_t* __restrict__ k_out, float* __restrict__ v_out,
    half_t* __restrict__ h_out,
    const float* __restrict__ lg, const float* __restrict__ lb,
    const float* __restrict__ xres, float* __restrict__ outp, half_t* __restrict__ xh_out,
    int M, int N, int K) {
    extern __shared__ __align__(16) char dyn[];
    half_t* sA = (half_t*)dyn;                    // [2][ASZ]
    half_t* sB = (half_t*)(dyn + 2 * ASZ * 2);    // [2][ASZ]
    float* red1 = (float*)(dyn + 4 * ASZ * 2);    // [128][4]
    float* red2 = red1 + 512;

    int tid = threadIdx.x;
    int warp = tid >> 5, lane = tid & 31;
    int wm = warp >> 2, wn = warp & 3;
    int mBase = blockIdx.y * 128;
    int nBase = blockIdx.x * 128;

    float acc[4][4][4];
#pragma unroll
    for (int a = 0; a < 4; a++)
#pragma unroll
        for (int b = 0; b < 4; b++)
#pragma unroll
            for (int c = 0; c < 4; c++) acc[a][b][c] = 0.f;

    const int lr = lane >> 2;
    const int lc2 = (lane & 3) * 2;
    const int ldRow = tid >> 3;          // 0..31 step -> x4 iters covers 128
    const int ldSeg = (tid & 7) * 8;     // halves

    int nk = K >> 6;

    // prologue: stage 0
#pragma unroll
    for (int it = 0; it < 4; it++) {
        int row = ldRow + it * 32;
        int ar = mBase + row;
        ar = (ar < M) ? ar : (M - 1);
        cpa16(&sA[row * LDSH + ldSeg], A + (size_t)ar * K + ldSeg);
        cpa16(&sB[row * LDSH + ldSeg], B + (size_t)(nBase + row) * K + ldSeg);
    }
    cpa_commit();

    for (int kt = 0; kt < nk; kt++) {
        if (kt + 1 < nk) {
            int st = ((kt + 1) & 1) * ASZ;
            int k0 = (kt + 1) << 6;
#pragma unroll
            for (int it = 0; it < 4; it++) {
                int row = ldRow + it * 32;
                int ar = mBase + row;
                ar = (ar < M) ? ar : (M - 1);
                cpa16(&sA[st + row * LDSH + ldSeg], A + (size_t)ar * K + k0 + ldSeg);
                cpa16(&sB[st + row * LDSH + ldSeg], B + (size_t)(nBase + row) * K + k0 + ldSeg);
            }
            cpa_commit();
            asm volatile("cp.async.wait_group 1;");
        } else {
            asm volatile("cp.async.wait_group 0;");
        }
        __syncthreads();

        const half_t* cA = sA + (kt & 1) * ASZ;
        const half_t* cB = sB + (kt & 1) * ASZ;
#pragma unroll
        for (int ks = 0; ks < 4; ks++) {
            int kc = ks * 16 + lc2;
            uint32_t af[4][4], bf[4][2];
#pragma unroll
            for (int mt = 0; mt < 4; mt++) {
                int r = wm * 64 + mt * 16 + lr;
                af[mt][0] = *(const uint32_t*)&cA[r * LDSH + kc];
                af[mt][1] = *(const uint32_t*)&cA[(r + 8) * LDSH + kc];
                af[mt][2] = *(const uint32_t*)&cA[r * LDSH + kc + 8];
                af[mt][3] = *(const uint32_t*)&cA[(r + 8) * LDSH + kc + 8];
            }
#pragma unroll
            for (int nt = 0; nt < 4; nt++) {
                int n = wn * 32 + nt * 8 + lr;
                bf[nt][0] = *(const uint32_t*)&cB[n * LDSH + kc];
                bf[nt][1] = *(const uint32_t*)&cB[n * LDSH + kc + 8];
            }
#pragma unroll
            for (int mt = 0; mt < 4; mt++)
#pragma unroll
                for (int nt = 0; nt < 4; nt++) mma16816h(acc[mt][nt], af[mt], bf[nt]);
        }
        __syncthreads();
    }

    // ---------------- epilogues ----------------
    if (MODE == 0) {
        // QKV split: no bias. nBase selects q/k/v.
#pragma unroll
        for (int mt = 0; mt < 4; mt++) {
            int r0 = mBase + wm * 64 + mt * 16 + lr;
            int r1 = r0 + 8;
#pragma unroll
            for (int nt = 0; nt < 4; nt++) {
                int c = nBase + wn * 32 + nt * 8 + lc2;
                float v00 = acc[mt][nt][0], v01 = acc[mt][nt][1];
                float v10 = acc[mt][nt][2], v11 = acc[mt][nt][3];
                if (nBase == 0) {
                    if (r0 < M) *(float2*)&q_out[(size_t)r0 * 128 + c] = make_float2(v00, v01);
                    if (r1 < M) *(float2*)&q_out[(size_t)r1 * 128 + c] = make_float2(v10, v11);
                } else if (nBase == 128) {
                    int c2 = c - 128;
                    if (r0 < M) *(__half2*)&k_out[(size_t)r0 * 128 + c2] = __floats2half2_rn(v00, v01);
                    if (r1 < M) *(__half2*)&k_out[(size_t)r1 * 128 + c2] = __floats2half2_rn(v10, v11);
                } else {
                    int c2 = c - 256;
                    if (r0 < M) *(float2*)&v_out[(size_t)r0 * 128 + c2] = make_float2(v00, v01);
                    if (r1 < M) *(float2*)&v_out[(size_t)r1 * 128 + c2] = make_float2(v10, v11);
                }
            }
        }
    } else if (MODE == 1) {
#pragma unroll
        for (int mt = 0; mt < 4; mt++) {
            int r0 = mBase + wm * 64 + mt * 16 + lr;
            int r1 = r0 + 8;
#pragma unroll
            for (int nt = 0; nt < 4; nt++) {
                int c = nBase + wn * 32 + nt * 8 + lc2;
                float b0 = bias[c], b1 = bias[c + 1];
                float v00 = fmaxf(acc[mt][nt][0] + b0, 0.f);
                float v01 = fmaxf(acc[mt][nt][1] + b1, 0.f);
                float v10 = fmaxf(acc[mt][nt][2] + b0, 0.f);
                float v11 = fmaxf(acc[mt][nt][3] + b1, 0.f);
                if (r0 < M) *(__half2*)&h_out[(size_t)r0 * N + c] = __floats2half2_rn(v00, v01);
                if (r1 < M) *(__half2*)&h_out[(size_t)r1 * N + c] = __floats2half2_rn(v10, v11);
            }
        }
    } else {
        // MODE 2: fused bias + residual + LayerNorm. N == 128, nBase == 0.
        float bv0[4], bv1[4], lgv0[4], lgv1[4], lbv0[4], lbv1[4];
#pragma unroll
        for (int nt = 0; nt < 4; nt++) {
            int c = wn * 32 + nt * 8 + lc2;
            bv0[nt] = bias[c]; bv1[nt] = bias[c + 1];
            lgv0[nt] = lg[c];  lgv1[nt] = lg[c + 1];
            lbv0[nt] = lb[c];  lbv1[nt] = lb[c + 1];
        }
        float rs1[4][2], rs2[4][2];
#pragma unroll
        for (int mt = 0; mt < 4; mt++) {
            int r0 = mBase + wm * 64 + mt * 16 + lr;
            int r1 = r0 + 8;
            int r0c = (r0 < M) ? r0 : (M - 1);
            int r1c = (r1 < M) ? r1 : (M - 1);
            rs1[mt][0] = rs2[mt][0] = rs1[mt][1] = rs2[mt][1] = 0.f;
#pragma unroll
            for (int nt = 0; nt < 4; nt++) {
                int c = wn * 32 + nt * 8 + lc2;
                float2 x0 = *(const float2*)&xres[(size_t)r0c * 128 + c];
                float2 x1 = *(const float2*)&xres[(size_t)r1c * 128 + c];
                float v00 = acc[mt][nt][0] + bv0[nt] + x0.x;
                float v01 = acc[mt][nt][1] + bv1[nt] + x0.y;
                float v10 = acc[mt][nt][2] + bv0[nt] + x1.x;
                float v11 = acc[mt][nt][3] + bv1[nt] + x1.y;
                acc[mt][nt][0] = v00; acc[mt][nt][1] = v01;
                acc[mt][nt][2] = v10; acc[mt][nt][3] = v11;
                rs1[mt][0] += v00 + v01;
                rs2[mt][0] += v00 * v00 + v01 * v01;
                rs1[mt][1] += v10 + v11;
                rs2[mt][1] += v10 * v10 + v11 * v11;
            }
#pragma unroll
            for (int s = 1; s <= 2; s <<= 1) {
                rs1[mt][0] += __shfl_xor_sync(0xffffffffu, rs1[mt][0], s);
                rs2[mt][0] += __shfl_xor_sync(0xffffffffu, rs2[mt][0], s);
                rs1[mt][1] += __shfl_xor_sync(0xffffffffu, rs1[mt][1], s);
                rs2[mt][1] += __shfl_xor_sync(0xffffffffu, rs2[mt][1], s);
            }
            if ((lane & 3) == 0) {
                int l0 = wm * 64 + mt * 16 + lr;
                red1[l0 * 4 + wn] = rs1[mt][0];
                red2[l0 * 4 + wn] = rs2[mt][0];
                red1[(l0 + 8) * 4 + wn] = rs1[mt][1];
                red2[(l0 + 8) * 4 + wn] = rs2[mt][1];
            }
        }
        __syncthreads();
#pragma unroll
        for (int mt = 0; mt < 4; mt++) {
            int l0 = wm * 64 + mt * 16 + lr;
            int r0 = mBase + l0;
            int r1 = r0 + 8;
            float s10 = red1[l0 * 4] + red1[l0 * 4 + 1] + red1[l0 * 4 + 2] + red1[l0 * 4 + 3];
            float s20 = red2[l0 * 4] + red2[l0 * 4 + 1] + red2[l0 * 4 + 2] + red2[l0 * 4 + 3];
            float s11 = red1[(l0 + 8) * 4] + red1[(l0 + 8) * 4 + 1] + red1[(l0 + 8) * 4 + 2] + red1[(l0 + 8) * 4 + 3];
            float s21 = red2[(l0 + 8) * 4] + red2[(l0 + 8) * 4 + 1] + red2[(l0 + 8) * 4 + 2] + red2[(l0 + 8) * 4 + 3];
            float mu0 = s10 * (1.f / 128.f);
            float inv0 = rsqrtf(s20 * (1.f / 128.f) - mu0 * mu0 + EPSV);
            float mu1 = s11 * (1.f / 128.f);
            float inv1 = rsqrtf(s21 * (1.f / 128.f) - mu1 * mu1 + EPSV);
#pragma unroll
            for (int nt = 0; nt < 4; nt++) {
                int c = wn * 32 + nt * 8 + lc2;
                float o00 = (acc[mt][nt][0] - mu0) * inv0 * lgv0[nt] + lbv0[nt];
                float o01 = (acc[mt][nt][1] - mu0) * inv0 * lgv1[nt] + lbv1[nt];
                float o10 = (acc[mt][nt][2] - mu1) * inv1 * lgv0[nt] + lbv0[nt];
                float o11 = (acc[mt][nt][3] - mu1) * inv1 * lgv1[nt] + lbv1[nt];
                if (r0 < M) {
                    *(float2*)&outp[(size_t)r0 * 128 + c] = make_float2(o00, o01);
                    *(__half2*)&xh_out[(size_t)r0 * 128 + c] = __floats2half2_rn(o00, o01);
                }
                if (r1 < M) {
                    *(float2*)&outp[(size_t)r1 * 128 + c] = make_float2(o10, o11);
                    *(__half2*)&xh_out[(size_t)r1 * 128 + c] = __floats2half2_rn(o10, o11);
                }
            }
        }
    }
}

// ---------------- edge attention + aggregation + residual + LN (warp per node) -------
__global__ __launch_bounds__(256) void agg_kernel(const float* __restrict__ eW1,
                                                  const float* __restrict__ eb1,
                                                  const float* __restrict__ eW2,
                                                  const float* __restrict__ eb2,
                                                  const float* __restrict__ lg,
                                                  const float* __restrict__ lb) {
    __shared__ float sW1[48];
    __shared__ float sb1[16];
    __shared__ float sW2[16 * 128];
    __shared__ float sb2[128];
    __shared__ float sg[128];
    __shared__ float sb[128];
    int tid = threadIdx.x;
    if (tid < 48) sW1[tid] = eW1[tid];
    if (tid < 16) sb1[tid] = eb1[tid];
    for (int i = tid; i < 2048; i += 256) sW2[i] = eW2[i];
    if (tid < 128) {
        sb2[tid] = eb2[tid];
        sg[tid] = lg[tid];
        sb[tid] = lb[tid];
    }
    __syncthreads();

    int warp = tid / 32, lane = tid % 32;
    int node = blockIdx.x * 8 + warp;
    if (node >= NN) return;

    int d0 = lane * 4;
    int head = lane >> 2;
    int i4 = lane & 3;
    int grp = lane & 28;

    float4 q = *(const float4*)&g_q[(size_t)node * DMM + d0];

    // per-node precompute: zq[uu] = Z[4*i4+uu][head]
    float zq[4] = {0.f, 0.f, 0.f, 0.f};
#pragma unroll
    for (int j = 0; j < 4; j++) {
        int jj = (i4 + j) & 3;
        int srcL = grp | jj;
        float q0 = __shfl_sync(0xffffffffu, q.x, srcL);
        float q1 = __shfl_sync(0xffffffffu, q.y, srcL);
        float q2 = __shfl_sync(0xffffffffu, q.z, srcL);
        float q3 = __shfl_sync(0xffffffffu, q.w, srcL);
        int col = head * 16 + jj * 4;
#pragma unroll
        for (int uu = 0; uu < 4; uu++) {
            const float* w = &sW2[(4 * i4 + uu) * 128 + col];
            zq[uu] += w[0] * q0 + w[1] * q1 + w[2] * q2 + w[3] * q3;
        }
    }
    float qb2 = q.x * sb2[d0] + q.y * sb2[d0 + 1] + q.z * sb2[d0 + 2] + q.w * sb2[d0 + 3];

    float w1a[4], w1b[4], w1c[4], w1d[4];
#pragma unroll
    for (int c = 0; c < 4; c++) {
        int u = 4 * i4 + c;
        w1a[c] = sW1[u]; w1b[c] = sW1[16 + u]; w1c[c] = sW1[32 + u]; w1d[c] = sb1[u];
    }

    float4 acc = make_float4(0.f, 0.f, 0.f, 0.f);
    int beg = g_off[node], end = g_off[node + 1];

    auto body = [&](const float4& es, const uint2& kh, const float4& v4) {
        float partial = qb2;
#pragma unroll
        for (int c = 0; c < 4; c++) {
            float h = fmaf(es.y, w1a[c], fmaf(es.z, w1b[c], fmaf(es.w, w1c[c], w1d[c])));
            partial = fmaf(fmaxf(h, 0.f), zq[c], partial);
        }
        float2 k01 = __half22float2(*(const __half2*)&kh.x);
        float2 k23 = __half22float2(*(const __half2*)&kh.y);
        float p = partial + q.x * k01.x + q.y * k01.y + q.z * k23.x + q.w * k23.y;
        p += __shfl_xor_sync(0xffffffffu, p, 1);
        p += __shfl_xor_sync(0xffffffffu, p, 2);
        float ex = __expf(p * 0.25f);
        float sum = ex;
        sum += __shfl_xor_sync(0xffffffffu, sum, 4);
        sum += __shfl_xor_sync(0xffffffffu, sum, 8);
        sum += __shfl_xor_sync(0xffffffffu, sum, 16);
        float attn = __fdividef(ex, sum);
        acc.x = fmaf(attn, v4.x, acc.x);
        acc.y = fmaf(attn, v4.y, acc.y);
        acc.z = fmaf(attn, v4.z, acc.z);
        acc.w = fmaf(attn, v4.w, acc.w);
    };

    int t = beg;
    for (; t + 2 <= end; t += 2) {
        float4 esa = g_es[t];
        float4 esb = g_es[t + 1];
        int ja = __float_as_int(esa.x);
        int jb = __float_as_int(esb.x);
        uint2 ka = *(const uint2*)&g_kh[(size_t)ja * DMM + d0];
        uint2 kb = *(const uint2*)&g_kh[(size_t)jb * DMM + d0];
        float4 va = *(const float4*)&g_v[(size_t)ja * DMM + d0];
        float4 vb = *(const float4*)&g_v[(size_t)jb * DMM + d0];
        body(esa, ka, va);
        body(esb, kb, vb);
    }
    if (t < end) {
        float4 es = g_es[t];
        int j = __float_as_int(es.x);
        uint2 kh = *(const uint2*)&g_kh[(size_t)j * DMM + d0];
        float4 v4 = *(const float4*)&g_v[(size_t)j * DMM + d0];
        body(es, kh, v4);
    }

    // residual + LayerNorm
    float4 xr = *(const float4*)&g_x[(size_t)node * DMM + d0];
    float4 r;
    r.x = xr.x + acc.x; r.y = xr.y + acc.y;
    r.z = xr.z + acc.z; r.w = xr.w + acc.w;
    float s1 = r.x + r.y + r.z + r.w;
    float s2 = r.x * r.x + r.y * r.y + r.z * r.z + r.w * r.w;
#pragma unroll
    for (int s = 16; s >= 1; s >>= 1) {
        s1 += __shfl_xor_sync(0xffffffffu, s1, s);
        s2 += __shfl_xor_sync(0xffffffffu, s2, s);
    }
    float mu = s1 * (1.f / 128.f);
    float var = s2 * (1.f / 128.f) - mu * mu;
    float inv = rsqrtf(var + EPSV);
    float4 o;
    o.x = (r.x - mu) * inv * sg[d0 + 0] + sb[d0 + 0];
    o.y = (r.y - mu) * inv * sg[d0 + 1] + sb[d0 + 1];
    o.z = (r.z - mu) * inv * sg[d0 + 2] + sb[d0 + 2];
    o.w = (r.w - mu) * inv * sg[d0 + 3] + sb[d0 + 3];
    *(float4*)&g_x[(size_t)node * DMM + d0] = o;
    *(__half2*)&g_xh[(size_t)node * DMM + d0] = __floats2half2_rn(o.x, o.y);
    *(__half2*)&g_xh[(size_t)node * DMM + d0 + 2] = __floats2half2_rn(o.z, o.w);
}

// ---------------- launch ----------------
extern "C" void kernel_launch(void* const* d_in, const int* in_sizes, int n_in,
                              void* d_out, int out_size) {
    const float* nf        = (const float*)d_in[0];
    const float* edge_attr = (const float*)d_in[1];
    const int*   edge_idx  = (const int*)d_in[2];
    const float* emb_W     = (const float*)d_in[3];
    const float* emb_b     = (const float*)d_in[4];
    const float* Wq        = (const float*)d_in[5];
    const float* Wk        = (const float*)d_in[6];
    const float* Wv        = (const float*)d_in[7];
    const float* eW1       = (const float*)d_in[8];
    const float* eb1       = (const float*)d_in[9];
    const float* eW2       = (const float*)d_in[10];
    const float* eb2       = (const float*)d_in[11];
    const float* ln_g      = (const float*)d_in[12];
    const float* ln_b      = (const float*)d_in[13];
    const float* fW1       = (const float*)d_in[14];
    const float* fb1       = (const float*)d_in[15];
    const float* fW2       = (const float*)d_in[16];
    const float* fb2       = (const float*)d_in[17];

    float *x, *qf, *vf;
    half_t *xh, *kh, *h1, *wq, *w1, *w2;
    cudaGetSymbolAddress((void**)&x, g_x);
    cudaGetSymbolAddress((void**)&xh, g_xh);
    cudaGetSymbolAddress((void**)&qf, g_q);
    cudaGetSymbolAddress((void**)&kh, g_kh);
    cudaGetSymbolAddress((void**)&vf, g_v);
    cudaGetSymbolAddress((void**)&h1, g_h1);
    cudaGetSymbolAddress((void**)&wq, g_Wqkv);
    cudaGetSymbolAddress((void**)&w1, g_W1);
    cudaGetSymbolAddress((void**)&w2, g_W2);

    cudaFuncSetAttribute(hgemm_kernel<0>, cudaFuncAttributeMaxDynamicSharedMemorySize, SMEMSZ);
    cudaFuncSetAttribute(hgemm_kernel<1>, cudaFuncAttributeMaxDynamicSharedMemorySize, SMEMSZ);
    cudaFuncSetAttribute(hgemm_kernel<2>, cudaFuncAttributeMaxDynamicSharedMemorySize, SMEMSZ);

    {
        const int TOT = LLN * (384 * 128 + 512 * 128 + 128 * 512);
        convw_kernel<<<(TOT + 255) / 256, 256>>>(Wq, Wk, Wv, fW1, fW2);
    }
    count_kernel<<<(EE + 255) / 256, 256>>>(edge_idx);
    scan_kernel<<<1, 1024>>>();
    fill_kernel<<<(EE + 255) / 256, 256>>>(edge_idx, edge_attr);
    embed_kernel<<<NN, 128>>>(nf, emb_W, emb_b);

    const int gRows = (NN + 127) / 128;  // 391
    for (int l = 0; l < LLN; l++) {
        // QKV: [N,128] @ [128,384] -> split q f32 / k f16 / v f32
        hgemm_kernel<0><<<dim3(3, gRows), 256, SMEMSZ>>>(
            xh, wq + (size_t)l * 384 * 128, nullptr,
            qf, kh, vf, nullptr, nullptr, nullptr, nullptr, nullptr, nullptr,
            NN, 384, 128);
        // edge attention + aggregation + residual + LN (updates x, xh)
        agg_kernel<<<(NN + 7) / 8, 256>>>(eW1 + l * 48, eb1 + l * 16,
                                          eW2 + l * 16 * 128, eb2 + l * 128,
                                          ln_g + l * 128, ln_b + l * 128);
        // FFN1: relu(x@W1 + b1) -> h1 fp16
        hgemm_kernel<1><<<dim3(4, gRows), 256, SMEMSZ>>>(
            xh, w1 + (size_t)l * 512 * 128, fb1 + l * 512,
            nullptr, nullptr, nullptr, h1, nullptr, nullptr, nullptr, nullptr, nullptr,
            NN, 512, 128);
        // FFN2 + fused residual + LN (last layer writes d_out)
        float* outp = (l == LLN - 1) ? (float*)d_out : x;
        hgemm_kernel<2><<<dim3(1, gRows), 256, SMEMSZ>>>(
            h1, w2 + (size_t)l * 128 * 512, fb2 + l * 128,
            nullptr, nullptr, nullptr, nullptr,
            ln_g + l * 128, ln_b + l * 128, x, outp, xh,
            NN, 128, 512);
    }
    (void)in_sizes; (void)n_in; (void)out_size;
}